// round 2
// baseline (speedup 1.0000x reference)
#include <cuda_runtime.h>
#include <math.h>

#define D 32
#define SEQ 2048
#define BATCH 2
#define NTOK (BATCH*SEQ)      // 4096
#define VOCAB 32000
#define FFH 128
#define EPS 1e-5f
#define INV_SQRT_D 0.17677669529663687f

// scratch (no cudaMalloc allowed)
__device__ float g_h[NTOK*D];   // pre-LN hidden (residual stream)
__device__ float g_q[NTOK*D];
__device__ float g_k[NTOK*D];
__device__ float g_v[NTOK*D];
__device__ float g_y[NTOK*D];   // post-block hidden

// ---------------------------------------------------------------------------
// Kernel A: h = emb[x] + pos ; hn = LN1(h) ; Q,K,V = hn @ W^T
// one warp per token, 4 warps per block
// ---------------------------------------------------------------------------
__global__ __launch_bounds__(128) void qkv_kernel(
    const int* __restrict__ x, const float* __restrict__ emb,
    const float* __restrict__ pos,
    const float* __restrict__ Wq, const float* __restrict__ Wk,
    const float* __restrict__ Wv,
    const float* __restrict__ g1, const float* __restrict__ bb1)
{
    __shared__ float wq_s[D*33], wk_s[D*33], wv_s[D*33];
    int tid = threadIdx.x;
    for (int i = tid; i < D*D; i += 128) {
        int e = i >> 5, d = i & 31;
        wq_s[e*33+d] = Wq[i];
        wk_s[e*33+d] = Wk[i];
        wv_s[e*33+d] = Wv[i];
    }
    __syncthreads();
    int w = tid >> 5, lane = tid & 31;
    int tok  = blockIdx.x*4 + w;
    int spos = tok & (SEQ-1);
    float h = emb[x[tok]*D + lane] + pos[spos*D + lane];
    g_h[tok*D + lane] = h;
    // LayerNorm over the 32 lanes
    float s1 = h, s2 = h*h;
    #pragma unroll
    for (int o = 16; o; o >>= 1) {
        s1 += __shfl_xor_sync(~0u, s1, o);
        s2 += __shfl_xor_sync(~0u, s2, o);
    }
    float mu  = s1 * (1.0f/D);
    float var = s2 * (1.0f/D) - mu*mu;
    float hn  = (h - mu) * rsqrtf(var + EPS) * g1[lane] + bb1[lane];
    float q = 0.f, k = 0.f, v = 0.f;
    #pragma unroll
    for (int d = 0; d < D; d++) {
        float hd = __shfl_sync(~0u, hn, d);
        q += hd * wq_s[lane*33+d];
        k += hd * wk_s[lane*33+d];
        v += hd * wv_s[lane*33+d];
    }
    g_q[tok*D+lane] = q;
    g_k[tok*D+lane] = k;
    g_v[tok*D+lane] = v;
}

// ---------------------------------------------------------------------------
// Kernel B: causal attention (flash-style, one warp per query) + residual
//           + LN2 + FFN (relu MLP) + residual
// 16 queries / block (512 thr), key/value tiles of 128 in smem
// ---------------------------------------------------------------------------
#define KC 128
#define QPB 16
#define KP 36   // padded row length (floats): conflict-free scalar & .128 access

__global__ __launch_bounds__(512) void attn_ffn_kernel(
    const float* __restrict__ ln2g, const float* __restrict__ ln2b,
    const float* __restrict__ W1,   const float* __restrict__ b1f,
    const float* __restrict__ W2,   const float* __restrict__ b2f)
{
    __shared__ float K_s[KC*KP];
    __shared__ float V_s[KC*KP];
    __shared__ float q_s[QPB*KP];
    __shared__ float ffh_s[QPB*FFH];

    int tid  = threadIdx.x;
    int w    = tid >> 5, lane = tid & 31;
    // heavy tiles (high seq position) first, interleaving the 2 batches
    int bid  = blockIdx.x;
    int t    = bid >> 1, bsel = bid & 1;
    int tile = bsel*128 + (127 - t);
    int q0   = tile * QPB;
    int batch = q0 / SEQ;
    int qrow  = q0 + w;
    int spos  = qrow & (SEQ-1);
    int sposmax = (q0 & (SEQ-1)) + QPB - 1;
    int kvbase  = batch * SEQ;

    q_s[w*KP + lane] = g_q[qrow*D + lane];

    float m = -INFINITY, l = 0.f, acc = 0.f;

    for (int kb = 0; kb <= sposmax; kb += KC) {
        int nload = min(KC, sposmax - kb + 1);
        int nfill = min(KC, (nload + 31) & ~31);
        for (int i = tid; i < nload*D; i += 512) {
            int r = i >> 5, d = i & 31;
            K_s[r*KP+d] = g_k[(kvbase+kb+r)*D + d];
            V_s[r*KP+d] = g_v[(kvbase+kb+r)*D + d];
        }
        for (int i = nload*D + tid; i < nfill*D; i += 512) {
            int r = i >> 5, d = i & 31;
            K_s[r*KP+d] = 0.f;
            V_s[r*KP+d] = 0.f;
        }
        __syncthreads();

        const float4* qp = (const float4*)&q_s[w*KP];
        int jmaxw = min(nload, spos - kb + 1);   // may be <= 0
        for (int jj = 0; jj < jmaxw; jj += 32) {
            int j = jj + lane;
            const float4* kp = (const float4*)&K_s[j*KP];
            float s = 0.f;
            #pragma unroll
            for (int d4 = 0; d4 < 8; d4++) {
                float4 qv = qp[d4];
                float4 kv = kp[d4];
                s += qv.x*kv.x + qv.y*kv.y + qv.z*kv.z + qv.w*kv.w;
            }
            s *= INV_SQRT_D;
            if (kb + j > spos) s = -1e30f;
            float mc = s;
            #pragma unroll
            for (int o = 16; o; o >>= 1)
                mc = fmaxf(mc, __shfl_xor_sync(~0u, mc, o));
            float mn   = fmaxf(m, mc);
            float corr = __expf(m - mn);
            float p    = __expf(s - mn);
            float ps   = p;
            #pragma unroll
            for (int o = 16; o; o >>= 1)
                ps += __shfl_xor_sync(~0u, ps, o);
            l = l*corr + ps;
            m = mn;
            acc *= corr;
            #pragma unroll
            for (int j2 = 0; j2 < 32; j2++) {
                float pj = __shfl_sync(~0u, p, j2);
                acc += pj * V_s[(jj+j2)*KP + lane];
            }
        }
        __syncthreads();
    }

    // epilogue: o + residual, LN2, FFN, residual
    float h  = g_h[qrow*D + lane];
    float h2 = acc / l + h;
    float s1 = h2, s2 = h2*h2;
    #pragma unroll
    for (int o = 16; o; o >>= 1) {
        s1 += __shfl_xor_sync(~0u, s1, o);
        s2 += __shfl_xor_sync(~0u, s2, o);
    }
    float mu  = s1 * (1.0f/D);
    float var = s2 * (1.0f/D) - mu*mu;
    float hn2 = (h2 - mu) * rsqrtf(var + EPS) * ln2g[lane] + ln2b[lane];

    float f0 = b1f[lane], f1 = b1f[32+lane], f2 = b1f[64+lane], f3 = b1f[96+lane];
    #pragma unroll
    for (int d = 0; d < D; d++) {
        float hd = __shfl_sync(~0u, hn2, d);
        f0 += hd * W1[(     lane)*D + d];
        f1 += hd * W1[(32 + lane)*D + d];
        f2 += hd * W1[(64 + lane)*D + d];
        f3 += hd * W1[(96 + lane)*D + d];
    }
    ffh_s[w*FFH +      lane] = fmaxf(f0, 0.f);
    ffh_s[w*FFH + 32 + lane] = fmaxf(f1, 0.f);
    ffh_s[w*FFH + 64 + lane] = fmaxf(f2, 0.f);
    ffh_s[w*FFH + 96 + lane] = fmaxf(f3, 0.f);
    __syncwarp();
    float y = b2f[lane] + h2;
    #pragma unroll
    for (int f = 0; f < FFH; f++)
        y += ffh_s[w*FFH + f] * W2[lane*FFH + f];
    g_y[qrow*D + lane] = y;
}

// ---------------------------------------------------------------------------
// Kernel C: logits = g_y @ Wo^T   (M=4096, N=32000, K=32), fp32 FFMA
// 64 rows x 128 cols per block; thread does 8 rows x 4 cols
// grid.x walks rows (few), grid.y walks vocab: CTAs launched back-to-back
// share the same g_y tile in L2.
// ---------------------------------------------------------------------------
__global__ __launch_bounds__(256) void logits_kernel(
    const float* __restrict__ Wo, float* __restrict__ out)
{
    __shared__ float wo_s[D*128];   // [k][c]
    __shared__ float h_s[64*D];     // [r][k]
    int tid = threadIdx.x;
    int R0 = blockIdx.x * 64;
    int C0 = blockIdx.y * 128;

    // load Wo tile, transposed to [k][c]
    #pragma unroll
    for (int i = tid; i < 128*8; i += 256) {
        int c = i & 127, k4 = i >> 7;
        float4 v = *(const float4*)&Wo[(C0+c)*D + k4*4];
        wo_s[(k4*4+0)*128 + c] = v.x;
        wo_s[(k4*4+1)*128 + c] = v.y;
        wo_s[(k4*4+2)*128 + c] = v.z;
        wo_s[(k4*4+3)*128 + c] = v.w;
    }
    // load h tile [r][k]
    #pragma unroll
    for (int i = tid; i < 64*8; i += 256) {
        int r = i >> 3, k4 = i & 7;
        *(float4*)&h_s[r*D + k4*4] = *(const float4*)&g_y[(R0+r)*D + k4*4];
    }
    __syncthreads();

    int c0 = (tid & 31) * 4;
    int r0 = (tid >> 5) * 8;
    float acc[8][4];
    #pragma unroll
    for (int r = 0; r < 8; r++)
        #pragma unroll
        for (int c = 0; c < 4; c++) acc[r][c] = 0.f;

    #pragma unroll
    for (int k4 = 0; k4 < 8; k4++) {
        float4 wk0 = *(const float4*)&wo_s[(k4*4+0)*128 + c0];
        float4 wk1 = *(const float4*)&wo_s[(k4*4+1)*128 + c0];
        float4 wk2 = *(const float4*)&wo_s[(k4*4+2)*128 + c0];
        float4 wk3 = *(const float4*)&wo_s[(k4*4+3)*128 + c0];
        #pragma unroll
        for (int r = 0; r < 8; r++) {
            float4 hv = *(const float4*)&h_s[(r0+r)*D + k4*4];
            acc[r][0] += hv.x*wk0.x + hv.y*wk1.x + hv.z*wk2.x + hv.w*wk3.x;
            acc[r][1] += hv.x*wk0.y + hv.y*wk1.y + hv.z*wk2.y + hv.w*wk3.y;
            acc[r][2] += hv.x*wk0.z + hv.y*wk1.z + hv.z*wk2.z + hv.w*wk3.z;
            acc[r][3] += hv.x*wk0.w + hv.y*wk1.w + hv.z*wk2.w + hv.w*wk3.w;
        }
    }
    #pragma unroll
    for (int r = 0; r < 8; r++) {
        float4 v = make_float4(acc[r][0], acc[r][1], acc[r][2], acc[r][3]);
        *(float4*)&out[(size_t)(R0+r0+r)*VOCAB + C0 + c0] = v;
    }
}

// ---------------------------------------------------------------------------
extern "C" void kernel_launch(void* const* d_in, const int* in_sizes, int n_in,
                              void* d_out, int out_size)
{
    const int*   x    = (const int*)d_in[0];
    const float* emb  = (const float*)d_in[1];
    const float* pos  = (const float*)d_in[2];
    const float* Wq   = (const float*)d_in[3];
    const float* Wk   = (const float*)d_in[4];
    const float* Wv   = (const float*)d_in[5];
    const float* ln1g = (const float*)d_in[6];
    const float* ln1b = (const float*)d_in[7];
    const float* ln2g = (const float*)d_in[8];
    const float* ln2b = (const float*)d_in[9];
    const float* W1   = (const float*)d_in[10];
    const float* b1   = (const float*)d_in[11];
    const float* W2   = (const float*)d_in[12];
    const float* b2   = (const float*)d_in[13];
    const float* Wo   = (const float*)d_in[14];
    float* out = (float*)d_out;

    qkv_kernel<<<NTOK/4, 128>>>(x, emb, pos, Wq, Wk, Wv, ln1g, ln1b);
    attn_ffn_kernel<<<NTOK/QPB, 512>>>(ln2g, ln2b, W1, b1, W2, b2);
    logits_kernel<<<dim3(NTOK/64, VOCAB/128), 256>>>(Wo, out);
}

// round 4
// speedup vs baseline: 2.1801x; 2.1801x over previous
#include <cuda_runtime.h>
#include <math.h>

#define D 32
#define SEQ 2048
#define BATCH 2
#define NTOK (BATCH*SEQ)      // 4096
#define VOCAB 32000
#define FFH 128
#define EPS 1e-5f
#define INV_SQRT_D 0.17677669529663687f

// scratch (no cudaMalloc allowed)
__device__ float g_h[NTOK*D];   // pre-LN hidden (residual stream)
__device__ float g_q[NTOK*D];
__device__ float g_k[NTOK*D];
__device__ float g_v[NTOK*D];
__device__ float g_y[NTOK*D];   // post-block hidden

__device__ __forceinline__ void ffma2(unsigned long long& d,
                                      unsigned long long a,
                                      unsigned long long b) {
    asm("fma.rn.f32x2 %0, %1, %2, %0;" : "+l"(d) : "l"(a), "l"(b));
}
__device__ __forceinline__ unsigned long long dup2(float x) {
    unsigned long long r;
    asm("mov.b64 %0, {%1, %1};" : "=l"(r) : "f"(x));
    return r;
}
__device__ __forceinline__ void unpack2(unsigned long long v, float& lo, float& hi) {
    asm("mov.b64 {%0, %1}, %2;" : "=f"(lo), "=f"(hi) : "l"(v));
}

// ---------------------------------------------------------------------------
// Kernel A: h = emb[x] + pos ; hn = LN1(h) ; Q,K,V = hn @ W^T
// one warp per token, 4 warps per block
// ---------------------------------------------------------------------------
__global__ __launch_bounds__(128) void qkv_kernel(
    const int* __restrict__ x, const float* __restrict__ emb,
    const float* __restrict__ pos,
    const float* __restrict__ Wq, const float* __restrict__ Wk,
    const float* __restrict__ Wv,
    const float* __restrict__ g1, const float* __restrict__ bb1)
{
    __shared__ float wq_s[D*33], wk_s[D*33], wv_s[D*33];
    int tid = threadIdx.x;
    for (int i = tid; i < D*D; i += 128) {
        int e = i >> 5, d = i & 31;
        wq_s[e*33+d] = Wq[i];
        wk_s[e*33+d] = Wk[i];
        wv_s[e*33+d] = Wv[i];
    }
    __syncthreads();
    int w = tid >> 5, lane = tid & 31;
    int tok  = blockIdx.x*4 + w;
    int spos = tok & (SEQ-1);
    float h = emb[x[tok]*D + lane] + pos[spos*D + lane];
    g_h[tok*D + lane] = h;
    float s1 = h, s2 = h*h;
    #pragma unroll
    for (int o = 16; o; o >>= 1) {
        s1 += __shfl_xor_sync(~0u, s1, o);
        s2 += __shfl_xor_sync(~0u, s2, o);
    }
    float mu  = s1 * (1.0f/D);
    float var = s2 * (1.0f/D) - mu*mu;
    float hn  = (h - mu) * rsqrtf(var + EPS) * g1[lane] + bb1[lane];
    float q = 0.f, k = 0.f, v = 0.f;
    #pragma unroll
    for (int d = 0; d < D; d++) {
        float hd = __shfl_sync(~0u, hn, d);
        q += hd * wq_s[lane*33+d];
        k += hd * wk_s[lane*33+d];
        v += hd * wv_s[lane*33+d];
    }
    g_q[tok*D+lane] = q;
    g_k[tok*D+lane] = k;
    g_v[tok*D+lane] = v;
}

// ---------------------------------------------------------------------------
// Kernel B: causal attention (fixed-max softmax: softmax is shift-invariant,
// masked scores underflow exp() to exactly 0 — matches reference exp(-1.77e8)=0)
// + residual + LN2 + FFN + residual. W1/W2 staged in smem, transposed.
// ---------------------------------------------------------------------------
#define KC 128
#define QPB 16
#define KP 36

__global__ __launch_bounds__(512) void attn_ffn_kernel(
    const float* __restrict__ ln2g, const float* __restrict__ ln2b,
    const float* __restrict__ W1,   const float* __restrict__ b1f,
    const float* __restrict__ W2,   const float* __restrict__ b2f)
{
    __shared__ float K_s[KC*KP];
    __shared__ float V_s[KC*KP];
    __shared__ float q_s[QPB*KP];
    __shared__ float ffh_s[QPB*FFH];
    __shared__ float W1t[D*132];    // [d][f]  f stride 1
    __shared__ float W2t[FFH*33];   // [f][dout]

    int tid  = threadIdx.x;
    int w    = tid >> 5, lane = tid & 31;

    // stage FFN weights (coalesced global reads, transposed smem writes)
    for (int i = tid; i < FFH*D; i += 512) {     // W1 [128][32]
        int f = i >> 5, d = i & 31;
        W1t[d*132 + f] = W1[i];
    }
    for (int i = tid; i < D*FFH; i += 512) {     // W2 [32][128]
        int dd = i >> 7, f = i & 127;
        W2t[f*33 + dd] = W2[i];
    }

    int bid  = blockIdx.x;
    int t    = bid >> 1, bsel = bid & 1;
    int tile = bsel*128 + (127 - t);
    int q0   = tile * QPB;
    int batch = q0 / SEQ;
    int qrow  = q0 + w;
    int spos  = qrow & (SEQ-1);
    int sposmax = (q0 & (SEQ-1)) + QPB - 1;
    int kvbase  = batch * SEQ;

    q_s[w*KP + lane] = g_q[qrow*D + lane];

    float l = 0.f, acc = 0.f;

    for (int kb = 0; kb <= sposmax; kb += KC) {
        int nload = min(KC, sposmax - kb + 1);
        int nfill = min(KC, (nload + 31) & ~31);
        // float4 loads: i indexes float4s, 8 per row
        for (int i = tid; i < nload*8; i += 512) {
            int r = i >> 3, d4 = (i & 7)*4;
            *(float4*)&K_s[r*KP+d4] = *(const float4*)&g_k[(kvbase+kb+r)*D + d4];
            *(float4*)&V_s[r*KP+d4] = *(const float4*)&g_v[(kvbase+kb+r)*D + d4];
        }
        for (int i = nload*8 + tid; i < nfill*8; i += 512) {
            int r = i >> 3, d4 = (i & 7)*4;
            *(float4*)&K_s[r*KP+d4] = make_float4(0.f,0.f,0.f,0.f);
            *(float4*)&V_s[r*KP+d4] = make_float4(0.f,0.f,0.f,0.f);
        }
        __syncthreads();

        const float4* qp = (const float4*)&q_s[w*KP];
        int jmaxw = min(nload, spos - kb + 1);   // may be <= 0
        for (int jj = 0; jj < jmaxw; jj += 32) {
            int j = jj + lane;
            const float4* kp = (const float4*)&K_s[j*KP];
            float s = 0.f;
            #pragma unroll
            for (int d4 = 0; d4 < 8; d4++) {
                float4 qv = qp[d4];
                float4 kv = kp[d4];
                s += qv.x*kv.x + qv.y*kv.y + qv.z*kv.z + qv.w*kv.w;
            }
            s *= INV_SQRT_D;
            if (kb + j > spos) s = -1e30f;       // exp -> exactly 0
            float p = __expf(s);
            l += p;
            #pragma unroll
            for (int j2 = 0; j2 < 32; j2++) {
                float pj = __shfl_sync(~0u, p, j2);
                acc += pj * V_s[(jj+j2)*KP + lane];
            }
        }
        __syncthreads();
    }

    // one l-reduction per query
    float ls = l;
    #pragma unroll
    for (int o = 16; o; o >>= 1) ls += __shfl_xor_sync(~0u, ls, o);

    float h  = g_h[qrow*D + lane];
    float h2 = acc / ls + h;
    float s1 = h2, s2 = h2*h2;
    #pragma unroll
    for (int o = 16; o; o >>= 1) {
        s1 += __shfl_xor_sync(~0u, s1, o);
        s2 += __shfl_xor_sync(~0u, s2, o);
    }
    float mu  = s1 * (1.0f/D);
    float var = s2 * (1.0f/D) - mu*mu;
    float hn2 = (h2 - mu) * rsqrtf(var + EPS) * ln2g[lane] + ln2b[lane];

    float f0 = b1f[lane], f1 = b1f[32+lane], f2 = b1f[64+lane], f3 = b1f[96+lane];
    #pragma unroll
    for (int d = 0; d < D; d++) {
        float hd = __shfl_sync(~0u, hn2, d);
        f0 += hd * W1t[d*132 +      lane];
        f1 += hd * W1t[d*132 + 32 + lane];
        f2 += hd * W1t[d*132 + 64 + lane];
        f3 += hd * W1t[d*132 + 96 + lane];
    }
    ffh_s[w*FFH +      lane] = fmaxf(f0, 0.f);
    ffh_s[w*FFH + 32 + lane] = fmaxf(f1, 0.f);
    ffh_s[w*FFH + 64 + lane] = fmaxf(f2, 0.f);
    ffh_s[w*FFH + 96 + lane] = fmaxf(f3, 0.f);
    __syncwarp();
    float y = b2f[lane] + h2;
    #pragma unroll
    for (int f = 0; f < FFH; f++)
        y += ffh_s[w*FFH + f] * W2t[f*33 + lane];
    g_y[qrow*D + lane] = y;
}

// ---------------------------------------------------------------------------
// Kernel C: logits = g_y @ Wo^T   (M=4096, N=32000, K=32)
// f32x2 packed FFMA2: 128x128 tile, thread = 8 rows x 8 cols (4 row-pairs).
// h-tile stored TRANSPOSED [k][r] so row-pairs come packed from LDS.128.
// w duplicated into both halves via mov.b64 (ALU pipe, off the FMA pipe).
// ---------------------------------------------------------------------------
__global__ __launch_bounds__(256) void logits_kernel(
    const float* __restrict__ Wo, float* __restrict__ out)
{
    __shared__ float ht[D*132];    // [k][r], 132-pad keeps 16B alignment
    __shared__ float wt[D*128];    // [k][c]
    int tid = threadIdx.x;
    int R0 = blockIdx.x * 128;
    int C0 = blockIdx.y * 128;

    // h tile: 128 rows x 32 k, coalesced float4 reads, transposed STS
    #pragma unroll
    for (int p = 0; p < 4; p++) {
        int idx = (p*256 + tid) * 4;
        int r = idx >> 5, k = idx & 31;
        float4 v = *(const float4*)&g_y[(R0+r)*D + k];
        ht[(k+0)*132 + r] = v.x;
        ht[(k+1)*132 + r] = v.y;
        ht[(k+2)*132 + r] = v.z;
        ht[(k+3)*132 + r] = v.w;
    }
    // Wo tile: rows C0..C0+127 are one CONTIGUOUS 16KB block -> coalesced
    const float4* wp = (const float4*)(Wo + (size_t)C0 * D);
    #pragma unroll
    for (int p = 0; p < 4; p++) {
        int fi = p*256 + tid;
        int idx = fi * 4;
        int c = idx >> 5, k = idx & 31;
        float4 v = wp[fi];
        wt[(k+0)*128 + c] = v.x;
        wt[(k+1)*128 + c] = v.y;
        wt[(k+2)*128 + c] = v.z;
        wt[(k+3)*128 + c] = v.w;
    }
    __syncthreads();

    int cx = tid & 15, ry = tid >> 4;
    int c0 = cx * 8, r0 = ry * 8;

    unsigned long long acc[4][8];
    #pragma unroll
    for (int rp = 0; rp < 4; rp++)
        #pragma unroll
        for (int c = 0; c < 8; c++) acc[rp][c] = 0ull;

    #pragma unroll
    for (int k = 0; k < D; k++) {
        // packed row-pairs straight from smem (rows contiguous in ht)
        ulonglong2 hA = *(const ulonglong2*)&ht[k*132 + r0];      // (r0,r1),(r2,r3)
        ulonglong2 hB = *(const ulonglong2*)&ht[k*132 + r0 + 4];  // (r4,r5),(r6,r7)
        float4 wA = *(const float4*)&wt[k*128 + c0];
        float4 wB = *(const float4*)&wt[k*128 + c0 + 4];
        unsigned long long wd[8];
        wd[0]=dup2(wA.x); wd[1]=dup2(wA.y); wd[2]=dup2(wA.z); wd[3]=dup2(wA.w);
        wd[4]=dup2(wB.x); wd[5]=dup2(wB.y); wd[6]=dup2(wB.z); wd[7]=dup2(wB.w);
        #pragma unroll
        for (int c = 0; c < 8; c++) {
            ffma2(acc[0][c], hA.x, wd[c]);
            ffma2(acc[1][c], hA.y, wd[c]);
            ffma2(acc[2][c], hB.x, wd[c]);
            ffma2(acc[3][c], hB.y, wd[c]);
        }
    }

    #pragma unroll
    for (int rp = 0; rp < 4; rp++) {
        float lo[8], hi[8];
        #pragma unroll
        for (int c = 0; c < 8; c++) unpack2(acc[rp][c], lo[c], hi[c]);
        size_t base0 = (size_t)(R0 + r0 + rp*2    ) * VOCAB + C0 + c0;
        size_t base1 = base0 + VOCAB;
        *(float4*)&out[base0    ] = make_float4(lo[0],lo[1],lo[2],lo[3]);
        *(float4*)&out[base0 + 4] = make_float4(lo[4],lo[5],lo[6],lo[7]);
        *(float4*)&out[base1    ] = make_float4(hi[0],hi[1],hi[2],hi[3]);
        *(float4*)&out[base1 + 4] = make_float4(hi[4],hi[5],hi[6],hi[7]);
    }
}

// ---------------------------------------------------------------------------
extern "C" void kernel_launch(void* const* d_in, const int* in_sizes, int n_in,
                              void* d_out, int out_size)
{
    const int*   x    = (const int*)d_in[0];
    const float* emb  = (const float*)d_in[1];
    const float* pos  = (const float*)d_in[2];
    const float* Wq   = (const float*)d_in[3];
    const float* Wk   = (const float*)d_in[4];
    const float* Wv   = (const float*)d_in[5];
    const float* ln1g = (const float*)d_in[6];
    const float* ln1b = (const float*)d_in[7];
    const float* ln2g = (const float*)d_in[8];
    const float* ln2b = (const float*)d_in[9];
    const float* W1   = (const float*)d_in[10];
    const float* b1   = (const float*)d_in[11];
    const float* W2   = (const float*)d_in[12];
    const float* b2   = (const float*)d_in[13];
    const float* Wo   = (const float*)d_in[14];
    float* out = (float*)d_out;

    qkv_kernel<<<NTOK/4, 128>>>(x, emb, pos, Wq, Wk, Wv, ln1g, ln1b);
    attn_ffn_kernel<<<NTOK/QPB, 512>>>(ln2g, ln2b, W1, b1, W2, b2);
    logits_kernel<<<dim3(NTOK/128, VOCAB/128), 256>>>(Wo, out);
}

// round 5
// speedup vs baseline: 2.3137x; 1.0613x over previous
#include <cuda_runtime.h>
#include <math.h>

#define D 32
#define SEQ 2048
#define BATCH 2
#define NTOK (BATCH*SEQ)      // 4096
#define VOCAB 32000
#define FFH 128
#define EPS 1e-5f
#define INV_SQRT_D 0.17677669529663687f

// scratch (no cudaMalloc allowed)
__device__ float g_h[NTOK*D];   // pre-LN hidden (residual stream)
__device__ float g_q[NTOK*D];
__device__ float g_k[NTOK*D];
__device__ float g_v[NTOK*D];
__device__ float g_y[NTOK*D];   // post-block hidden

__device__ __forceinline__ void ffma2(unsigned long long& d,
                                      unsigned long long a,
                                      unsigned long long b) {
    asm("fma.rn.f32x2 %0, %1, %2, %0;" : "+l"(d) : "l"(a), "l"(b));
}
__device__ __forceinline__ unsigned long long dup2(float x) {
    unsigned long long r;
    asm("mov.b64 %0, {%1, %1};" : "=l"(r) : "f"(x));
    return r;
}
__device__ __forceinline__ void unpack2(unsigned long long v, float& lo, float& hi) {
    asm("mov.b64 {%0, %1}, %2;" : "=f"(lo), "=f"(hi) : "l"(v));
}

// ---------------------------------------------------------------------------
// Kernel A: h = emb[x] + pos ; hn = LN1(h) ; Q,K,V = hn @ W^T
// ---------------------------------------------------------------------------
__global__ __launch_bounds__(128) void qkv_kernel(
    const int* __restrict__ x, const float* __restrict__ emb,
    const float* __restrict__ pos,
    const float* __restrict__ Wq, const float* __restrict__ Wk,
    const float* __restrict__ Wv,
    const float* __restrict__ g1, const float* __restrict__ bb1)
{
    __shared__ float wq_s[D*33], wk_s[D*33], wv_s[D*33];
    int tid = threadIdx.x;
    for (int i = tid; i < D*D; i += 128) {
        int e = i >> 5, d = i & 31;
        wq_s[e*33+d] = Wq[i];
        wk_s[e*33+d] = Wk[i];
        wv_s[e*33+d] = Wv[i];
    }
    __syncthreads();
    int w = tid >> 5, lane = tid & 31;
    int tok  = blockIdx.x*4 + w;
    int spos = tok & (SEQ-1);
    float h = emb[x[tok]*D + lane] + pos[spos*D + lane];
    g_h[tok*D + lane] = h;
    float s1 = h, s2 = h*h;
    #pragma unroll
    for (int o = 16; o; o >>= 1) {
        s1 += __shfl_xor_sync(~0u, s1, o);
        s2 += __shfl_xor_sync(~0u, s2, o);
    }
    float mu  = s1 * (1.0f/D);
    float var = s2 * (1.0f/D) - mu*mu;
    float hn  = (h - mu) * rsqrtf(var + EPS) * g1[lane] + bb1[lane];
    float q = 0.f, k = 0.f, v = 0.f;
    #pragma unroll
    for (int d = 0; d < D; d++) {
        float hd = __shfl_sync(~0u, hn, d);
        q += hd * wq_s[lane*33+d];
        k += hd * wk_s[lane*33+d];
        v += hd * wv_s[lane*33+d];
    }
    g_q[tok*D+lane] = q;
    g_k[tok*D+lane] = k;
    g_v[tok*D+lane] = v;
}

// ---------------------------------------------------------------------------
// Kernel B: causal attention (fixed-max softmax — shift-invariant; masked
// scores underflow exp() to exactly 0, matching the reference)
// + residual + LN2 + FFN + residual.
// q held in registers; PV uses 4 independent accumulators (chain-breaking).
// ---------------------------------------------------------------------------
#define KC 128
#define QPB 16
#define KP 36

__global__ __launch_bounds__(512) void attn_ffn_kernel(
    const float* __restrict__ ln2g, const float* __restrict__ ln2b,
    const float* __restrict__ W1,   const float* __restrict__ b1f,
    const float* __restrict__ W2,   const float* __restrict__ b2f)
{
    __shared__ float K_s[KC*KP];
    __shared__ float V_s[KC*KP];
    __shared__ float ffh_s[QPB*FFH];
    __shared__ float W1t[D*132];    // [d][f]
    __shared__ float W2t[FFH*33];   // [f][dout]

    int tid  = threadIdx.x;
    int w    = tid >> 5, lane = tid & 31;

    for (int i = tid; i < FFH*D; i += 512) {     // W1 [128][32]
        int f = i >> 5, d = i & 31;
        W1t[d*132 + f] = W1[i];
    }
    for (int i = tid; i < D*FFH; i += 512) {     // W2 [32][128]
        int dd = i >> 7, f = i & 127;
        W2t[f*33 + dd] = W2[i];
    }

    int bid  = blockIdx.x;
    int t    = bid >> 1, bsel = bid & 1;
    int tile = bsel*128 + (127 - t);
    int q0   = tile * QPB;
    int batch = q0 / SEQ;
    int qrow  = q0 + w;
    int spos  = qrow & (SEQ-1);
    int sposmax = (q0 & (SEQ-1)) + QPB - 1;
    int kvbase  = batch * SEQ;

    // q in registers (whole 32-dim vector per lane)
    float4 qv0 = *(const float4*)&g_q[qrow*D +  0];
    float4 qv1 = *(const float4*)&g_q[qrow*D +  4];
    float4 qv2 = *(const float4*)&g_q[qrow*D +  8];
    float4 qv3 = *(const float4*)&g_q[qrow*D + 12];
    float4 qv4 = *(const float4*)&g_q[qrow*D + 16];
    float4 qv5 = *(const float4*)&g_q[qrow*D + 20];
    float4 qv6 = *(const float4*)&g_q[qrow*D + 24];
    float4 qv7 = *(const float4*)&g_q[qrow*D + 28];

    float l = 0.f;
    float a0 = 0.f, a1 = 0.f, a2 = 0.f, a3 = 0.f;

    for (int kb = 0; kb <= sposmax; kb += KC) {
        int nload = min(KC, sposmax - kb + 1);
        int nfill = min(KC, (nload + 31) & ~31);
        for (int i = tid; i < nload*8; i += 512) {
            int r = i >> 3, d4 = (i & 7)*4;
            *(float4*)&K_s[r*KP+d4] = *(const float4*)&g_k[(kvbase+kb+r)*D + d4];
            *(float4*)&V_s[r*KP+d4] = *(const float4*)&g_v[(kvbase+kb+r)*D + d4];
        }
        for (int i = nload*8 + tid; i < nfill*8; i += 512) {
            int r = i >> 3, d4 = (i & 7)*4;
            *(float4*)&K_s[r*KP+d4] = make_float4(0.f,0.f,0.f,0.f);
            *(float4*)&V_s[r*KP+d4] = make_float4(0.f,0.f,0.f,0.f);
        }
        __syncthreads();

        int jmaxw = min(nload, spos - kb + 1);   // may be <= 0
        for (int jj = 0; jj < jmaxw; jj += 32) {
            int j = jj + lane;
            const float4* kp = (const float4*)&K_s[j*KP];
            float4 k0 = kp[0], k1 = kp[1], k2 = kp[2], k3 = kp[3];
            float4 k4 = kp[4], k5 = kp[5], k6 = kp[6], k7 = kp[7];
            float sA = qv0.x*k0.x + qv0.y*k0.y + qv0.z*k0.z + qv0.w*k0.w
                     + qv1.x*k1.x + qv1.y*k1.y + qv1.z*k1.z + qv1.w*k1.w;
            float sB = qv2.x*k2.x + qv2.y*k2.y + qv2.z*k2.z + qv2.w*k2.w
                     + qv3.x*k3.x + qv3.y*k3.y + qv3.z*k3.z + qv3.w*k3.w;
            float sC = qv4.x*k4.x + qv4.y*k4.y + qv4.z*k4.z + qv4.w*k4.w
                     + qv5.x*k5.x + qv5.y*k5.y + qv5.z*k5.z + qv5.w*k5.w;
            float sD = qv6.x*k6.x + qv6.y*k6.y + qv6.z*k6.z + qv6.w*k6.w
                     + qv7.x*k7.x + qv7.y*k7.y + qv7.z*k7.z + qv7.w*k7.w;
            float s = ((sA + sB) + (sC + sD)) * INV_SQRT_D;
            if (kb + j > spos) s = -1e30f;       // exp -> exactly 0
            float p = __expf(s);
            l += p;
            #pragma unroll
            for (int j2 = 0; j2 < 8; j2++) {
                float p0 = __shfl_sync(~0u, p, j2);
                float p1 = __shfl_sync(~0u, p, j2 + 8);
                float p2 = __shfl_sync(~0u, p, j2 + 16);
                float p3 = __shfl_sync(~0u, p, j2 + 24);
                a0 += p0 * V_s[(jj+j2     )*KP + lane];
                a1 += p1 * V_s[(jj+j2 +  8)*KP + lane];
                a2 += p2 * V_s[(jj+j2 + 16)*KP + lane];
                a3 += p3 * V_s[(jj+j2 + 24)*KP + lane];
            }
        }
        __syncthreads();
    }

    float acc = (a0 + a1) + (a2 + a3);
    float ls = l;
    #pragma unroll
    for (int o = 16; o; o >>= 1) ls += __shfl_xor_sync(~0u, ls, o);

    float h  = g_h[qrow*D + lane];
    float h2 = acc / ls + h;
    float s1 = h2, s2 = h2*h2;
    #pragma unroll
    for (int o = 16; o; o >>= 1) {
        s1 += __shfl_xor_sync(~0u, s1, o);
        s2 += __shfl_xor_sync(~0u, s2, o);
    }
    float mu  = s1 * (1.0f/D);
    float var = s2 * (1.0f/D) - mu*mu;
    float hn2 = (h2 - mu) * rsqrtf(var + EPS) * ln2g[lane] + ln2b[lane];

    float f0 = b1f[lane], f1 = b1f[32+lane], f2 = b1f[64+lane], f3 = b1f[96+lane];
    #pragma unroll
    for (int d = 0; d < D; d++) {
        float hd = __shfl_sync(~0u, hn2, d);
        f0 += hd * W1t[d*132 +      lane];
        f1 += hd * W1t[d*132 + 32 + lane];
        f2 += hd * W1t[d*132 + 64 + lane];
        f3 += hd * W1t[d*132 + 96 + lane];
    }
    ffh_s[w*FFH +      lane] = fmaxf(f0, 0.f);
    ffh_s[w*FFH + 32 + lane] = fmaxf(f1, 0.f);
    ffh_s[w*FFH + 64 + lane] = fmaxf(f2, 0.f);
    ffh_s[w*FFH + 96 + lane] = fmaxf(f3, 0.f);
    __syncwarp();
    float y = b2f[lane] + h2;
    #pragma unroll
    for (int f = 0; f < FFH; f++)
        y += ffh_s[w*FFH + f] * W2t[f*33 + lane];
    g_y[qrow*D + lane] = y;
}

// ---------------------------------------------------------------------------
// Kernel C: logits = g_y @ Wo^T   (M=4096, N=32000, K=32)
// f32x2 packed FFMA2: 128x128 tile, thread = 8 rows x 8 cols (4 row-pairs).
// ---------------------------------------------------------------------------
__global__ __launch_bounds__(256) void logits_kernel(
    const float* __restrict__ Wo, float* __restrict__ out)
{
    __shared__ float ht[D*132];    // [k][r]
    __shared__ float wt[D*128];    // [k][c]
    int tid = threadIdx.x;
    int R0 = blockIdx.x * 128;
    int C0 = blockIdx.y * 128;

    #pragma unroll
    for (int p = 0; p < 4; p++) {
        int idx = (p*256 + tid) * 4;
        int r = idx >> 5, k = idx & 31;
        float4 v = *(const float4*)&g_y[(R0+r)*D + k];
        ht[(k+0)*132 + r] = v.x;
        ht[(k+1)*132 + r] = v.y;
        ht[(k+2)*132 + r] = v.z;
        ht[(k+3)*132 + r] = v.w;
    }
    const float4* wp = (const float4*)(Wo + (size_t)C0 * D);
    #pragma unroll
    for (int p = 0; p < 4; p++) {
        int fi = p*256 + tid;
        int idx = fi * 4;
        int c = idx >> 5, k = idx & 31;
        float4 v = wp[fi];
        wt[(k+0)*128 + c] = v.x;
        wt[(k+1)*128 + c] = v.y;
        wt[(k+2)*128 + c] = v.z;
        wt[(k+3)*128 + c] = v.w;
    }
    __syncthreads();

    int cx = tid & 15, ry = tid >> 4;
    int c0 = cx * 8, r0 = ry * 8;

    unsigned long long acc[4][8];
    #pragma unroll
    for (int rp = 0; rp < 4; rp++)
        #pragma unroll
        for (int c = 0; c < 8; c++) acc[rp][c] = 0ull;

    #pragma unroll
    for (int k = 0; k < D; k++) {
        ulonglong2 hA = *(const ulonglong2*)&ht[k*132 + r0];
        ulonglong2 hB = *(const ulonglong2*)&ht[k*132 + r0 + 4];
        float4 wA = *(const float4*)&wt[k*128 + c0];
        float4 wB = *(const float4*)&wt[k*128 + c0 + 4];
        unsigned long long wd[8];
        wd[0]=dup2(wA.x); wd[1]=dup2(wA.y); wd[2]=dup2(wA.z); wd[3]=dup2(wA.w);
        wd[4]=dup2(wB.x); wd[5]=dup2(wB.y); wd[6]=dup2(wB.z); wd[7]=dup2(wB.w);
        #pragma unroll
        for (int c = 0; c < 8; c++) {
            ffma2(acc[0][c], hA.x, wd[c]);
            ffma2(acc[1][c], hA.y, wd[c]);
            ffma2(acc[2][c], hB.x, wd[c]);
            ffma2(acc[3][c], hB.y, wd[c]);
        }
    }

    #pragma unroll
    for (int rp = 0; rp < 4; rp++) {
        float lo[8], hi[8];
        #pragma unroll
        for (int c = 0; c < 8; c++) unpack2(acc[rp][c], lo[c], hi[c]);
        size_t base0 = (size_t)(R0 + r0 + rp*2    ) * VOCAB + C0 + c0;
        size_t base1 = base0 + VOCAB;
        *(float4*)&out[base0    ] = make_float4(lo[0],lo[1],lo[2],lo[3]);
        *(float4*)&out[base0 + 4] = make_float4(lo[4],lo[5],lo[6],lo[7]);
        *(float4*)&out[base1    ] = make_float4(hi[0],hi[1],hi[2],hi[3]);
        *(float4*)&out[base1 + 4] = make_float4(hi[4],hi[5],hi[6],hi[7]);
    }
}

// ---------------------------------------------------------------------------
extern "C" void kernel_launch(void* const* d_in, const int* in_sizes, int n_in,
                              void* d_out, int out_size)
{
    const int*   x    = (const int*)d_in[0];
    const float* emb  = (const float*)d_in[1];
    const float* pos  = (const float*)d_in[2];
    const float* Wq   = (const float*)d_in[3];
    const float* Wk   = (const float*)d_in[4];
    const float* Wv   = (const float*)d_in[5];
    const float* ln1g = (const float*)d_in[6];
    const float* ln1b = (const float*)d_in[7];
    const float* ln2g = (const float*)d_in[8];
    const float* ln2b = (const float*)d_in[9];
    const float* W1   = (const float*)d_in[10];
    const float* b1   = (const float*)d_in[11];
    const float* W2   = (const float*)d_in[12];
    const float* b2   = (const float*)d_in[13];
    const float* Wo   = (const float*)d_in[14];
    float* out = (float*)d_out;

    qkv_kernel<<<NTOK/4, 128>>>(x, emb, pos, Wq, Wk, Wv, ln1g, ln1b);
    attn_ffn_kernel<<<NTOK/QPB, 512>>>(ln2g, ln2b, W1, b1, W2, b2);
    logits_kernel<<<dim3(NTOK/128, VOCAB/128), 256>>>(Wo, out);
}